// round 2
// baseline (speedup 1.0000x reference)
#include <cuda_runtime.h>
#include <cuda_bf16.h>
#include <cstdint>

// OctreeMaxUnpool:
//   out[(i*8 + c)*C + k] = (indices[i*C + k] == c) ? data[nempty_idx[i]*C + k] : 0
//
// R2: 8 threads per row, each handling 2 adjacent float4 lanes (32 B).
//   - 4 independent 128-bit loads per thread (more MLP, fewer warps in flight)
//   - __stcs streaming stores for the write-once 1 GB output, keeping the
//     gathered `data` rows (which have ~32% duplication) resident in L2.

#define NUM_CHILDREN 8

template <int C4>   // C4 = C/4 (float4 lanes per row); threads/row = C4/2
__global__ void __launch_bounds__(256)
octree_unpool_vec2_kernel(const float4* __restrict__ data,
                          const int4*  __restrict__ indices,
                          const int*   __restrict__ nempty_idx,
                          float4*      __restrict__ out,
                          int num)
{
    constexpr int TPR = C4 / 2;            // threads per row
    int gtid = blockIdx.x * blockDim.x + threadIdx.x;
    int i    = gtid / TPR;                 // row index
    int l    = gtid - i * TPR;             // pair-lane within row
    if (i >= num) return;

    int lane = l * 2;

    int src = __ldg(&nempty_idx[i]);
    const float4* dp = data    + (long long)src * C4 + lane;
    const int4*   ip = indices + (long long)i   * C4 + lane;

    float4 d0 = __ldg(dp);
    float4 d1 = __ldg(dp + 1);
    int4   x0 = __ldg(ip);
    int4   x1 = __ldg(ip + 1);

    long long base = (long long)i * (NUM_CHILDREN * C4) + lane;
#pragma unroll
    for (int c = 0; c < NUM_CHILDREN; c++) {
        float4 o0, o1;
        o0.x = (x0.x == c) ? d0.x : 0.0f;
        o0.y = (x0.y == c) ? d0.y : 0.0f;
        o0.z = (x0.z == c) ? d0.z : 0.0f;
        o0.w = (x0.w == c) ? d0.w : 0.0f;
        o1.x = (x1.x == c) ? d1.x : 0.0f;
        o1.y = (x1.y == c) ? d1.y : 0.0f;
        o1.z = (x1.z == c) ? d1.z : 0.0f;
        o1.w = (x1.w == c) ? d1.w : 0.0f;
        __stcs(out + base + (long long)c * C4,     o0);
        __stcs(out + base + (long long)c * C4 + 1, o1);
    }
}

// Generic-C vectorized kernel (runtime C4) for C % 4 == 0 but C != 64.
__global__ void __launch_bounds__(256)
octree_unpool_vec_dyn_kernel(const float4* __restrict__ data,
                             const int4*  __restrict__ indices,
                             const int*   __restrict__ nempty_idx,
                             float4*      __restrict__ out,
                             int num, int C4)
{
    int gtid = blockIdx.x * blockDim.x + threadIdx.x;
    int i    = gtid / C4;
    int lane = gtid - i * C4;
    if (i >= num) return;

    int src = __ldg(&nempty_idx[i]);
    float4 d  = __ldg(&data[(long long)src * C4 + lane]);
    int4   ix = __ldg(&indices[(long long)i * C4 + lane]);

    long long base = (long long)i * (NUM_CHILDREN * C4) + lane;
#pragma unroll
    for (int c = 0; c < NUM_CHILDREN; c++) {
        float4 o;
        o.x = (ix.x == c) ? d.x : 0.0f;
        o.y = (ix.y == c) ? d.y : 0.0f;
        o.z = (ix.z == c) ? d.z : 0.0f;
        o.w = (ix.w == c) ? d.w : 0.0f;
        __stcs(out + base + (long long)c * C4, o);
    }
}

// Scalar fallback for arbitrary C.
__global__ void __launch_bounds__(256)
octree_unpool_scalar_kernel(const float* __restrict__ data,
                            const int*   __restrict__ indices,
                            const int*   __restrict__ nempty_idx,
                            float*       __restrict__ out,
                            int num, int C)
{
    long long gtid = (long long)blockIdx.x * blockDim.x + threadIdx.x;
    long long total = (long long)num * C;
    if (gtid >= total) return;
    int i = (int)(gtid / C);
    int k = (int)(gtid - (long long)i * C);

    int src  = __ldg(&nempty_idx[i]);
    float dv = __ldg(&data[(long long)src * C + k]);
    int   ix = __ldg(&indices[(long long)i * C + k]);

    long long base = ((long long)i * NUM_CHILDREN) * C + k;
#pragma unroll
    for (int c = 0; c < NUM_CHILDREN; c++) {
        out[base + (long long)c * C] = (ix == c) ? dv : 0.0f;
    }
}

extern "C" void kernel_launch(void* const* d_in, const int* in_sizes, int n_in,
                              void* d_out, int out_size)
{
    const float* data       = (const float*)d_in[0];
    const int*   indices    = (const int*)d_in[1];
    const int*   nempty_idx = (const int*)d_in[2];
    // d_in[3] = depth (unused: the gather is already expressed by nempty_idx)

    float* out = (float*)d_out;

    int num = in_sizes[2];
    int C   = (num > 0) ? (in_sizes[1] / num) : 0;

    if (num <= 0 || C <= 0) return;

    if (C == 64) {
        constexpr int C4  = 16;
        constexpr int TPR = C4 / 2;   // 8 threads per row
        long long threads = (long long)num * TPR;
        int block = 256;
        int grid  = (int)((threads + block - 1) / block);
        octree_unpool_vec2_kernel<C4><<<grid, block>>>(
            (const float4*)data, (const int4*)indices, nempty_idx,
            (float4*)out, num);
    } else if ((C & 3) == 0) {
        int C4 = C >> 2;
        long long threads = (long long)num * C4;
        int block = 256;
        int grid  = (int)((threads + block - 1) / block);
        octree_unpool_vec_dyn_kernel<<<grid, block>>>(
            (const float4*)data, (const int4*)indices, nempty_idx,
            (float4*)out, num, C4);
    } else {
        long long threads = (long long)num * C;
        int block = 256;
        int grid  = (int)((threads + block - 1) / block);
        octree_unpool_scalar_kernel<<<grid, block>>>(
            data, indices, nempty_idx, out, num, C);
    }
}

// round 3
// speedup vs baseline: 2.1107x; 2.1107x over previous
#include <cuda_runtime.h>
#include <cuda_bf16.h>
#include <cstdint>

// OctreeMaxUnpool:
//   out[(i*8 + c)*C + k] = (indices[i*C + k] == c) ? data[nempty_idx[i]*C + k] : 0
//
// R3: revert to R1's layout (16 threads/row, 1 float4 per thread) so every
// warp-wide STG.128 writes fully contiguous 256-B spans (complete 128-B
// lines per instruction). Add __stcs streaming stores on the write-once
// output ONLY on this full-line pattern — R2 showed .cs + partial-line
// store instructions inflates DRAM write traffic by ~50%.

#define NUM_CHILDREN 8

template <int C4>
__global__ void __launch_bounds__(256)
octree_unpool_vec_kernel(const float4* __restrict__ data,
                         const int4*  __restrict__ indices,
                         const int*   __restrict__ nempty_idx,
                         float4*      __restrict__ out,
                         int num)
{
    int gtid = blockIdx.x * blockDim.x + threadIdx.x;
    int i    = gtid / C4;          // row index
    int lane = gtid - i * C4;      // float4 lane within row
    if (i >= num) return;

    int src = __ldg(&nempty_idx[i]);
    float4 d  = __ldg(&data[(long long)src * C4 + lane]);
    int4   ix = __ldg(&indices[(long long)i * C4 + lane]);

    long long base = (long long)i * (NUM_CHILDREN * C4) + lane;
#pragma unroll
    for (int c = 0; c < NUM_CHILDREN; c++) {
        float4 o;
        o.x = (ix.x == c) ? d.x : 0.0f;
        o.y = (ix.y == c) ? d.y : 0.0f;
        o.z = (ix.z == c) ? d.z : 0.0f;
        o.w = (ix.w == c) ? d.w : 0.0f;
        __stcs(out + base + (long long)c * C4, o);
    }
}

// Generic-C vectorized kernel (runtime C4) for C % 4 == 0 but C != 64.
__global__ void __launch_bounds__(256)
octree_unpool_vec_dyn_kernel(const float4* __restrict__ data,
                             const int4*  __restrict__ indices,
                             const int*   __restrict__ nempty_idx,
                             float4*      __restrict__ out,
                             int num, int C4)
{
    int gtid = blockIdx.x * blockDim.x + threadIdx.x;
    int i    = gtid / C4;
    int lane = gtid - i * C4;
    if (i >= num) return;

    int src = __ldg(&nempty_idx[i]);
    float4 d  = __ldg(&data[(long long)src * C4 + lane]);
    int4   ix = __ldg(&indices[(long long)i * C4 + lane]);

    long long base = (long long)i * (NUM_CHILDREN * C4) + lane;
#pragma unroll
    for (int c = 0; c < NUM_CHILDREN; c++) {
        float4 o;
        o.x = (ix.x == c) ? d.x : 0.0f;
        o.y = (ix.y == c) ? d.y : 0.0f;
        o.z = (ix.z == c) ? d.z : 0.0f;
        o.w = (ix.w == c) ? d.w : 0.0f;
        out[base + (long long)c * C4] = o;
    }
}

// Scalar fallback for arbitrary C.
__global__ void __launch_bounds__(256)
octree_unpool_scalar_kernel(const float* __restrict__ data,
                            const int*   __restrict__ indices,
                            const int*   __restrict__ nempty_idx,
                            float*       __restrict__ out,
                            int num, int C)
{
    long long gtid = (long long)blockIdx.x * blockDim.x + threadIdx.x;
    long long total = (long long)num * C;
    if (gtid >= total) return;
    int i = (int)(gtid / C);
    int k = (int)(gtid - (long long)i * C);

    int src  = __ldg(&nempty_idx[i]);
    float dv = __ldg(&data[(long long)src * C + k]);
    int   ix = __ldg(&indices[(long long)i * C + k]);

    long long base = ((long long)i * NUM_CHILDREN) * C + k;
#pragma unroll
    for (int c = 0; c < NUM_CHILDREN; c++) {
        out[base + (long long)c * C] = (ix == c) ? dv : 0.0f;
    }
}

extern "C" void kernel_launch(void* const* d_in, const int* in_sizes, int n_in,
                              void* d_out, int out_size)
{
    const float* data       = (const float*)d_in[0];
    const int*   indices    = (const int*)d_in[1];
    const int*   nempty_idx = (const int*)d_in[2];
    // d_in[3] = depth (unused: the gather is already expressed by nempty_idx)

    float* out = (float*)d_out;

    int num = in_sizes[2];
    int C   = (num > 0) ? (in_sizes[1] / num) : 0;

    if (num <= 0 || C <= 0) return;

    if (C == 64) {
        constexpr int C4 = 16;
        long long threads = (long long)num * C4;
        int block = 256;
        int grid  = (int)((threads + block - 1) / block);
        octree_unpool_vec_kernel<C4><<<grid, block>>>(
            (const float4*)data, (const int4*)indices, nempty_idx,
            (float4*)out, num);
    } else if ((C & 3) == 0) {
        int C4 = C >> 2;
        long long threads = (long long)num * C4;
        int block = 256;
        int grid  = (int)((threads + block - 1) / block);
        octree_unpool_vec_dyn_kernel<<<grid, block>>>(
            (const float4*)data, (const int4*)indices, nempty_idx,
            (float4*)out, num, C4);
    } else {
        long long threads = (long long)num * C;
        int block = 256;
        int grid  = (int)((threads + block - 1) / block);
        octree_unpool_scalar_kernel<<<grid, block>>>(
            data, indices, nempty_idx, out, num, C);
    }
}

// round 4
// speedup vs baseline: 2.1266x; 1.0075x over previous
#include <cuda_runtime.h>
#include <cuda_bf16.h>
#include <cstdint>

// OctreeMaxUnpool:
//   out[(i*8 + c)*C + k] = (indices[i*C + k] == c) ? data[nempty_idx[i]*C + k] : 0
//
// R4: one warp per row (C=64). Each warp writes its row's full 8*C*4 = 2048 B
// output span with 4 store instructions, each covering 512 fully contiguous
// ascending bytes (max write-combining friendliness). Thread t loads the
// data/index float4 for lane (t&15) — upper half-warp duplicates lower half's
// addresses, which dedup to the same sectors within the warp request — and
// writes children (t>>4)+2j for j=0..3 at that lane.

#define NUM_CHILDREN 8

__device__ __forceinline__ float4 child_select(int4 ix, float4 d, int c) {
    float4 o;
    o.x = (ix.x == c) ? d.x : 0.0f;
    o.y = (ix.y == c) ? d.y : 0.0f;
    o.z = (ix.z == c) ? d.z : 0.0f;
    o.w = (ix.w == c) ? d.w : 0.0f;
    return o;
}

// C = 64 fast path: one warp per row.
__global__ void __launch_bounds__(256)
octree_unpool_warprow_kernel(const float4* __restrict__ data,
                             const int4*  __restrict__ indices,
                             const int*   __restrict__ nempty_idx,
                             float4*      __restrict__ out,
                             int num)
{
    constexpr int C4 = 16;                       // float4 lanes per row
    int gtid = blockIdx.x * blockDim.x + threadIdx.x;
    int i    = gtid >> 5;                        // row = warp id
    int t    = gtid & 31;                        // lane in warp
    if (i >= num) return;

    int l = t & 15;                              // float4 lane within row
    int h = t >> 4;                              // half-warp id (0/1)

    int src = __ldg(&nempty_idx[i]);
    float4 d  = __ldg(&data[(long long)src * C4 + l]);
    int4   ix = __ldg(&indices[(long long)i * C4 + l]);

    float4* rowbase = out + (long long)i * (NUM_CHILDREN * C4);
#pragma unroll
    for (int j = 0; j < 4; j++) {
        int c = h + 2 * j;                       // child slot this thread writes
        float4 o = child_select(ix, d, c);
        // position within row = c*16 + l = t + 32*j  (ascending contiguous)
        __stcs(rowbase + t + 32 * j, o);
    }
}

// Generic-C vectorized kernel (runtime C4) for C % 4 == 0 but C != 64.
__global__ void __launch_bounds__(256)
octree_unpool_vec_dyn_kernel(const float4* __restrict__ data,
                             const int4*  __restrict__ indices,
                             const int*   __restrict__ nempty_idx,
                             float4*      __restrict__ out,
                             int num, int C4)
{
    int gtid = blockIdx.x * blockDim.x + threadIdx.x;
    int i    = gtid / C4;
    int lane = gtid - i * C4;
    if (i >= num) return;

    int src = __ldg(&nempty_idx[i]);
    float4 d  = __ldg(&data[(long long)src * C4 + lane]);
    int4   ix = __ldg(&indices[(long long)i * C4 + lane]);

    long long base = (long long)i * (NUM_CHILDREN * C4) + lane;
#pragma unroll
    for (int c = 0; c < NUM_CHILDREN; c++) {
        out[base + (long long)c * C4] = child_select(ix, d, c);
    }
}

// Scalar fallback for arbitrary C.
__global__ void __launch_bounds__(256)
octree_unpool_scalar_kernel(const float* __restrict__ data,
                            const int*   __restrict__ indices,
                            const int*   __restrict__ nempty_idx,
                            float*       __restrict__ out,
                            int num, int C)
{
    long long gtid = (long long)blockIdx.x * blockDim.x + threadIdx.x;
    long long total = (long long)num * C;
    if (gtid >= total) return;
    int i = (int)(gtid / C);
    int k = (int)(gtid - (long long)i * C);

    int src  = __ldg(&nempty_idx[i]);
    float dv = __ldg(&data[(long long)src * C + k]);
    int   ix = __ldg(&indices[(long long)i * C + k]);

    long long base = ((long long)i * NUM_CHILDREN) * C + k;
#pragma unroll
    for (int c = 0; c < NUM_CHILDREN; c++) {
        out[base + (long long)c * C] = (ix == c) ? dv : 0.0f;
    }
}

extern "C" void kernel_launch(void* const* d_in, const int* in_sizes, int n_in,
                              void* d_out, int out_size)
{
    const float* data       = (const float*)d_in[0];
    const int*   indices    = (const int*)d_in[1];
    const int*   nempty_idx = (const int*)d_in[2];
    // d_in[3] = depth (unused: the gather is already expressed by nempty_idx)

    float* out = (float*)d_out;

    int num = in_sizes[2];
    int C   = (num > 0) ? (in_sizes[1] / num) : 0;

    if (num <= 0 || C <= 0) return;

    if (C == 64) {
        long long threads = (long long)num * 32;   // one warp per row
        int block = 256;
        int grid  = (int)((threads + block - 1) / block);
        octree_unpool_warprow_kernel<<<grid, block>>>(
            (const float4*)data, (const int4*)indices, nempty_idx,
            (float4*)out, num);
    } else if ((C & 3) == 0) {
        int C4 = C >> 2;
        long long threads = (long long)num * C4;
        int block = 256;
        int grid  = (int)((threads + block - 1) / block);
        octree_unpool_vec_dyn_kernel<<<grid, block>>>(
            (const float4*)data, (const int4*)indices, nempty_idx,
            (float4*)out, num, C4);
    } else {
        long long threads = (long long)num * C;
        int block = 256;
        int grid  = (int)((threads + block - 1) / block);
        octree_unpool_scalar_kernel<<<grid, block>>>(
            data, indices, nempty_idx, out, num, C);
    }
}